// round 1
// baseline (speedup 1.0000x reference)
#include <cuda_runtime.h>
#include <math.h>

#define NB   8
#define TT   2048
#define DD   1024
#define MTOT (NB * TT)   // 16384

#define BM 128
#define BN 128
#define BK 16
#define PAD 4

// Scratch (allocation-free rule: __device__ globals)
__device__ float g_q[(size_t)MTOT * DD];
__device__ float g_k[(size_t)MTOT * DD];
__device__ float g_v[(size_t)MTOT * DD];
__device__ float g_temp[MTOT];
__device__ float g_scores[(size_t)NB * TT * TT];

// ---------------------------------------------------------------------------
// Generic tiled GEMM.
//   BT=true :  C = A * B^T   (A: MxK row-major, B: NxK row-major)
//   BT=false:  C = A * B     (A: MxK row-major, B: KxN row-major)
// Optional per-row scale in epilogue (for temp * scores).
// Batched via blockIdx.z with element strides sA/sB/sC/sScale.
// M % 128 == 0, N % 128 == 0, K % 16 == 0 assumed (true for all uses here).
// ---------------------------------------------------------------------------
template <bool BT>
__global__ __launch_bounds__(256, 2)
void gemm_kernel(const float* __restrict__ A, const float* __restrict__ Bm,
                 float* __restrict__ C, int M, int N, int K,
                 size_t sA, size_t sB, size_t sC,
                 const float* __restrict__ rowscale, int sScale)
{
    __shared__ float As[BK][BM + PAD];
    __shared__ float Bs[BK][BN + PAD];

    const int z = blockIdx.z;
    A  += (size_t)z * sA;
    Bm += (size_t)z * sB;
    C  += (size_t)z * sC;
    if (rowscale) rowscale += (size_t)z * sScale;

    const int tid  = threadIdx.x;
    const int row0 = blockIdx.y * BM;
    const int col0 = blockIdx.x * BN;
    const int tm   = tid / 16;   // 0..15
    const int tn   = tid % 16;   // 0..15

    float acc[8][8];
#pragma unroll
    for (int i = 0; i < 8; i++)
#pragma unroll
        for (int j = 0; j < 8; j++) acc[i][j] = 0.0f;

    for (int k0 = 0; k0 < K; k0 += BK) {
        // ---- load A tile (transposed into As[k][m]) ----
#pragma unroll
        for (int t = tid; t < 512; t += 256) {
            int i = t >> 2, j4 = t & 3;
            float4 a = *(const float4*)(A + (size_t)(row0 + i) * K + k0 + j4 * 4);
            As[j4 * 4 + 0][i] = a.x;
            As[j4 * 4 + 1][i] = a.y;
            As[j4 * 4 + 2][i] = a.z;
            As[j4 * 4 + 3][i] = a.w;
        }
        // ---- load B tile ----
        if (BT) {
#pragma unroll
            for (int t = tid; t < 512; t += 256) {
                int i = t >> 2, j4 = t & 3;
                float4 b = *(const float4*)(Bm + (size_t)(col0 + i) * K + k0 + j4 * 4);
                Bs[j4 * 4 + 0][i] = b.x;
                Bs[j4 * 4 + 1][i] = b.y;
                Bs[j4 * 4 + 2][i] = b.z;
                Bs[j4 * 4 + 3][i] = b.w;
            }
        } else {
#pragma unroll
            for (int t = tid; t < 512; t += 256) {
                int j = t >> 5, i4 = t & 31;
                float4 b = *(const float4*)(Bm + (size_t)(k0 + j) * N + col0 + i4 * 4);
                *(float4*)&Bs[j][i4 * 4] = b;
            }
        }
        __syncthreads();

#pragma unroll
        for (int kk = 0; kk < BK; kk++) {
            float4 a0 = *(const float4*)&As[kk][tm * 4];
            float4 a1 = *(const float4*)&As[kk][tm * 4 + 64];
            float4 b0 = *(const float4*)&Bs[kk][tn * 4];
            float4 b1 = *(const float4*)&Bs[kk][tn * 4 + 64];
            float ar[8] = {a0.x, a0.y, a0.z, a0.w, a1.x, a1.y, a1.z, a1.w};
            float br[8] = {b0.x, b0.y, b0.z, b0.w, b1.x, b1.y, b1.z, b1.w};
#pragma unroll
            for (int i = 0; i < 8; i++)
#pragma unroll
                for (int j = 0; j < 8; j++)
                    acc[i][j] += ar[i] * br[j];
        }
        __syncthreads();
    }

    // ---- epilogue ----
#pragma unroll
    for (int i = 0; i < 8; i++) {
        int m = row0 + tm * 4 + (i & 3) + (i >> 2) * 64;
        float s = 1.0f;
        if (rowscale) s = rowscale[m];
        float4 o0 = make_float4(acc[i][0] * s, acc[i][1] * s, acc[i][2] * s, acc[i][3] * s);
        float4 o1 = make_float4(acc[i][4] * s, acc[i][5] * s, acc[i][6] * s, acc[i][7] * s);
        *(float4*)(C + (size_t)m * N + col0 + tn * 4)      = o0;
        *(float4*)(C + (size_t)m * N + col0 + tn * 4 + 64) = o1;
    }
}

// ---------------------------------------------------------------------------
// Reductions
// ---------------------------------------------------------------------------
__device__ __forceinline__ float warp_sum(float v) {
#pragma unroll
    for (int o = 16; o > 0; o >>= 1) v += __shfl_xor_sync(0xffffffffu, v, o);
    return v;
}
__device__ __forceinline__ float warp_max(float v) {
#pragma unroll
    for (int o = 16; o > 0; o >>= 1) v = fmaxf(v, __shfl_xor_sync(0xffffffffu, v, o));
    return v;
}

// ---------------------------------------------------------------------------
// temp[row] = clip(hbar / (||q_row|| + eps), 0.1, 5.0)   (one block per row)
// ---------------------------------------------------------------------------
__global__ void temp_kernel(const float* __restrict__ q,
                            const float* __restrict__ hbar,
                            float* __restrict__ temp)
{
    int row = blockIdx.x;
    const float4* qr = (const float4*)(q + (size_t)row * DD);
    int tid = threadIdx.x;                   // 256 threads, D/4 = 256 float4s
    float4 a = qr[tid];
    float s = a.x * a.x + a.y * a.y + a.z * a.z + a.w * a.w;
    s = warp_sum(s);
    __shared__ float red[8];
    if ((tid & 31) == 0) red[tid >> 5] = s;
    __syncthreads();
    if (tid == 0) {
        float t = 0.0f;
#pragma unroll
        for (int i = 0; i < 8; i++) t += red[i];
        float n  = sqrtf(t);
        float tv = hbar[0] / (n + 1e-8f);
        tv = fminf(fmaxf(tv, 0.1f), 5.0f);
        temp[row] = tv;
    }
}

// ---------------------------------------------------------------------------
// In-place row softmax over TT=2048 columns (one block of 256 per row)
// ---------------------------------------------------------------------------
__global__ void softmax_kernel(float* __restrict__ sc)
{
    size_t row = blockIdx.x;
    float* p = sc + row * (size_t)TT;
    int tid = threadIdx.x;

    float v[8];
    float mx = -3.4e38f;
#pragma unroll
    for (int j = 0; j < 8; j++) {
        v[j] = p[tid + j * 256];
        mx = fmaxf(mx, v[j]);
    }
    mx = warp_max(mx);
    __shared__ float red[8];
    __shared__ float bval;
    if ((tid & 31) == 0) red[tid >> 5] = mx;
    __syncthreads();
    if (tid == 0) {
        float m = red[0];
#pragma unroll
        for (int i = 1; i < 8; i++) m = fmaxf(m, red[i]);
        bval = m;
    }
    __syncthreads();
    mx = bval;

    float s = 0.0f;
#pragma unroll
    for (int j = 0; j < 8; j++) {
        v[j] = expf(v[j] - mx);
        s += v[j];
    }
    s = warp_sum(s);
    __syncthreads();   // red[] reuse: ensure all max-phase reads done
    if ((tid & 31) == 0) red[tid >> 5] = s;
    __syncthreads();
    if (tid == 0) {
        float t = 0.0f;
#pragma unroll
        for (int i = 0; i < 8; i++) t += red[i];
        bval = t;
    }
    __syncthreads();
    float inv = 1.0f / bval;
#pragma unroll
    for (int j = 0; j < 8; j++) p[tid + j * 256] = v[j] * inv;
}

// ---------------------------------------------------------------------------
extern "C" void kernel_launch(void* const* d_in, const int* in_sizes, int n_in,
                              void* d_out, int out_size)
{
    const float* x  = (const float*)d_in[0];
    const float* Wq = (const float*)d_in[1];
    const float* Wk = (const float*)d_in[2];
    const float* Wv = (const float*)d_in[3];
    const float* hb = (const float*)d_in[4];
    float* out = (float*)d_out;

    float *q, *k, *v, *tmp, *sc;
    cudaGetSymbolAddress((void**)&q,   g_q);
    cudaGetSymbolAddress((void**)&k,   g_k);
    cudaGetSymbolAddress((void**)&v,   g_v);
    cudaGetSymbolAddress((void**)&tmp, g_temp);
    cudaGetSymbolAddress((void**)&sc,  g_scores);

    dim3 blk(256);

    // 1) QKV projections:  C[m,e] = sum_d x[m,d] * W[e,d]  ->  A * B^T
    dim3 g_qkv(DD / BN, MTOT / BM, 1);
    gemm_kernel<true><<<g_qkv, blk>>>(x, Wq, q, MTOT, DD, DD, 0, 0, 0, nullptr, 0);
    gemm_kernel<true><<<g_qkv, blk>>>(x, Wk, k, MTOT, DD, DD, 0, 0, 0, nullptr, 0);
    gemm_kernel<true><<<g_qkv, blk>>>(x, Wv, v, MTOT, DD, DD, 0, 0, 0, nullptr, 0);

    // 2) per-query adaptive temperature
    temp_kernel<<<MTOT, 256>>>(q, hb, tmp);

    // 3) scores = (q @ k^T) * temp[row]   batched over NB
    dim3 g_sc(TT / BN, TT / BM, NB);
    gemm_kernel<true><<<g_sc, blk>>>(q, k, sc, TT, TT, DD,
                                     (size_t)TT * DD, (size_t)TT * DD,
                                     (size_t)TT * TT, tmp, TT);

    // 4) row softmax
    softmax_kernel<<<MTOT, 256>>>(sc);

    // 5) out = attn @ v   batched over NB  (A * B form)
    dim3 g_out(DD / BN, TT / BM, NB);
    gemm_kernel<false><<<g_out, blk>>>(sc, v, out, TT, DD, TT,
                                       (size_t)TT * TT, (size_t)TT * DD,
                                       (size_t)TT * DD, nullptr, 0);
}